// round 13
// baseline (speedup 1.0000x reference)
#include <cuda_runtime.h>

#define BB 8
#define LL 512
#define KK 512
#define MM 64
#define NN 64
#define PDIM 64
#define DD 64

// scratch (device globals; no allocations)
__device__ float g_ssT [BB * KK * LL];        // 8 MB  exp(scores) stored [b][k][l]
__device__ float g_sum4[BB * 4 * LL];         // 64 KB per-(b,ktile) partial row sums
__device__ float g_vkc [BB * KK * NN];        // 1 MB
__device__ float g_tmp4[BB * 4 * LL * NN];    // 4 MB  split-K partial tmp

#define KB_STRIDE 68
#define QT_STRIDE 68

// ============ KV: vkc[b,k,n] = sum_p vk[b,k,p,n] * vexp[b,k,p] (14.0us) ============
__global__ void __launch_bounds__(256) kv_kernel(
    const float* __restrict__ vk, const float* __restrict__ vexp) {
    __shared__ float sve[256];
    __shared__ __align__(16) float4 red[256];
    int t = threadIdx.x;
    int bk0 = blockIdx.x * 4;

    sve[t] = vexp[(size_t)bk0 * PDIM + t];
    __syncthreads();

    int slab = t >> 6;
    int tt = t & 63;
    int n4 = tt & 15;
    int pg = tt >> 4;
    const float4* vk4 = (const float4*)(vk + (size_t)(bk0 + slab) * PDIM * NN);
    const float* ve = &sve[slab * 64];
    float4 acc = make_float4(0.f, 0.f, 0.f, 0.f);
#pragma unroll
    for (int i = 0; i < 16; i++) {
        int p = pg * 16 + i;
        float4 a = vk4[p * 16 + n4];
        float e = ve[p];
        acc.x += a.x * e; acc.y += a.y * e; acc.z += a.z * e; acc.w += a.w * e;
    }
    red[t] = acc;
    __syncthreads();
    if (tt < 16) {
        float4 r0 = red[slab * 64 + n4];
        float4 r1 = red[slab * 64 + 16 + n4];
        float4 r2 = red[slab * 64 + 32 + n4];
        float4 r3 = red[slab * 64 + 48 + n4];
        float4 o = make_float4(r0.x + r1.x + r2.x + r3.x, r0.y + r1.y + r2.y + r3.y,
                               r0.z + r1.z + r2.z + r3.z, r0.w + r1.w + r2.w + r3.w);
        *(float4*)&g_vkc[(size_t)(bk0 + slab) * NN + n4 * 4] = o;
    }
}

// ============ SC: scores^T + exp + partial row sums (runs CONCURRENT with KV) ============
__global__ void __launch_bounds__(256) sc_kernel(
    const float* __restrict__ q, const float* __restrict__ k,
    const float* __restrict__ scale_p) {
    extern __shared__ float s[];
    float* kbuf = s;                        // [128][KB_STRIDE]
    float* qT   = s + 128 * KB_STRIDE;      // [64][QT_STRIDE]
    float* ssum = qT + 64 * QT_STRIDE;      // [64]
    int t = threadIdx.x;
    int bid = blockIdx.x;
    int b  = bid >> 5;
    int r  = bid & 31;
    int l0 = (r >> 2) * 64;
    int kt = r & 3;
    int k0 = kt * 128;

#pragma unroll
    for (int j = 0; j < 8; j++) {
        int v = t + j * 256;
        int row = v >> 4, c4 = v & 15;
        float4 x = *(const float4*)&k[((size_t)(b * KK + k0 + row)) * DD + c4 * 4];
        *(float4*)&kbuf[row * KB_STRIDE + c4 * 4] = x;
    }
#pragma unroll
    for (int i = 0; i < 4; i++) {
        int l = (t >> 4) + 16 * i;
        int d4 = t & 15;
        float4 x = *(const float4*)&q[((size_t)(b * LL + l0 + l)) * DD + d4 * 4];
        qT[(d4 * 4 + 0) * QT_STRIDE + l] = x.x;
        qT[(d4 * 4 + 1) * QT_STRIDE + l] = x.y;
        qT[(d4 * 4 + 2) * QT_STRIDE + l] = x.z;
        qT[(d4 * 4 + 3) * QT_STRIDE + l] = x.w;
    }
    if (t < 64) ssum[t] = 0.f;
    __syncthreads();

    int tkg = t >> 3;          // k rows tkg*4..+3
    int tlg = t & 7;           // l groups (tlg*4 and 32+tlg*4)
    float acc[4][8];
#pragma unroll
    for (int a = 0; a < 4; a++)
#pragma unroll
        for (int c = 0; c < 8; c++) acc[a][c] = 0.f;

#pragma unroll 2
    for (int d0 = 0; d0 < DD; d0 += 4) {
        float4 kv4[4];
#pragma unroll
        for (int ki = 0; ki < 4; ki++)
            kv4[ki] = *(float4*)&kbuf[(tkg * 4 + ki) * KB_STRIDE + d0];
#pragma unroll
        for (int dd = 0; dd < 4; dd++) {
            float4 qa = *(float4*)&qT[(d0 + dd) * QT_STRIDE + tlg * 4];
            float4 qb = *(float4*)&qT[(d0 + dd) * QT_STRIDE + 32 + tlg * 4];
            float kd[4];
            kd[0] = ((float*)&kv4[0])[dd];
            kd[1] = ((float*)&kv4[1])[dd];
            kd[2] = ((float*)&kv4[2])[dd];
            kd[3] = ((float*)&kv4[3])[dd];
#pragma unroll
            for (int ki = 0; ki < 4; ki++) {
                acc[ki][0] += kd[ki] * qa.x;
                acc[ki][1] += kd[ki] * qa.y;
                acc[ki][2] += kd[ki] * qa.z;
                acc[ki][3] += kd[ki] * qa.w;
                acc[ki][4] += kd[ki] * qb.x;
                acc[ki][5] += kd[ki] * qb.y;
                acc[ki][6] += kd[ki] * qb.z;
                acc[ki][7] += kd[ki] * qb.w;
            }
        }
    }

    float scale = *scale_p;
    float sacc[8];
#pragma unroll
    for (int j = 0; j < 8; j++) sacc[j] = 0.f;
#pragma unroll
    for (int ki = 0; ki < 4; ki++) {
        float4 e0, e1;
        e0.x = __expf(acc[ki][0] * scale);
        e0.y = __expf(acc[ki][1] * scale);
        e0.z = __expf(acc[ki][2] * scale);
        e0.w = __expf(acc[ki][3] * scale);
        e1.x = __expf(acc[ki][4] * scale);
        e1.y = __expf(acc[ki][5] * scale);
        e1.z = __expf(acc[ki][6] * scale);
        e1.w = __expf(acc[ki][7] * scale);
        sacc[0] += e0.x; sacc[1] += e0.y; sacc[2] += e0.z; sacc[3] += e0.w;
        sacc[4] += e1.x; sacc[5] += e1.y; sacc[6] += e1.z; sacc[7] += e1.w;
        size_t base = ((size_t)(b * KK + k0 + tkg * 4 + ki)) * LL + l0;
        *(float4*)&g_ssT[base + tlg * 4]      = e0;
        *(float4*)&g_ssT[base + 32 + tlg * 4] = e1;
    }
#pragma unroll
    for (int j = 0; j < 4; j++) atomicAdd(&ssum[tlg * 4 + j], sacc[j]);
#pragma unroll
    for (int j = 0; j < 4; j++) atomicAdd(&ssum[32 + tlg * 4 + j], sacc[4 + j]);
    __syncthreads();
    if (t < 64) g_sum4[((size_t)(b * 4 + kt)) * LL + l0 + t] = ssum[t];
}

// ============ K2: tmp4 = E^T(chunk) outer-product vkc(chunk), split-K ============
#define ES 68
#define VS 68
__global__ void __launch_bounds__(256) k2_kernel() {
    extern __shared__ float s[];
    float* Es = s;                 // [128][ES]
    float* Vs = s + 128 * ES;      // [128][VS]
    int t = threadIdx.x;
    int bid = blockIdx.x;
    int b  = bid >> 5;
    int r  = bid & 31;
    int l0 = (r >> 2) * 64;
    int ks = r & 3;
    int k0 = ks * 128;

#pragma unroll
    for (int j = 0; j < 8; j++) {
        int v = t + j * 256;
        int row = v >> 4, c4 = v & 15;
        float4 x = *(const float4*)&g_ssT[((size_t)(b * KK + k0 + row)) * LL + l0 + c4 * 4];
        *(float4*)&Es[row * ES + c4 * 4] = x;
    }
#pragma unroll
    for (int j = 0; j < 8; j++) {
        int v = t + j * 256;
        int row = v >> 4, c4 = v & 15;
        float4 x = *(const float4*)&g_vkc[((size_t)(b * KK + k0 + row)) * NN + c4 * 4];
        *(float4*)&Vs[row * VS + c4 * 4] = x;
    }
    __syncthreads();

    int tn = t >> 4, tl = t & 15;   // 4l x 4n per thread
    float acc[4][4];
#pragma unroll
    for (int a = 0; a < 4; a++)
#pragma unroll
        for (int c = 0; c < 4; c++) acc[a][c] = 0.f;
#pragma unroll 4
    for (int kk = 0; kk < 128; kk++) {
        float4 e4 = *(float4*)&Es[kk * ES + tl * 4];
        float4 v4 = *(float4*)&Vs[kk * VS + tn * 4];
        float ee[4] = {e4.x, e4.y, e4.z, e4.w};
        float vv[4] = {v4.x, v4.y, v4.z, v4.w};
#pragma unroll
        for (int li = 0; li < 4; li++)
#pragma unroll
            for (int nj = 0; nj < 4; nj++)
                acc[li][nj] += ee[li] * vv[nj];
    }
#pragma unroll
    for (int li = 0; li < 4; li++) {
        int l = l0 + tl * 4 + li;
        float4 o = {acc[li][0], acc[li][1], acc[li][2], acc[li][3]};
        *(float4*)&g_tmp4[(((size_t)(b * 4 + ks)) * LL + l) * NN + tn * 4] = o;
    }
}

// ============ K3: attn = vq @ tmp (combined+normalized), residual + LN (18.7us) ============
__global__ void __launch_bounds__(256) k3_kernel(
    const float* __restrict__ q, const float* __restrict__ vq,
    const float* __restrict__ gamma, const float* __restrict__ beta,
    float* __restrict__ out) {
    int bl = blockIdx.x;             // b*512 + l
    int b = bl >> 9, l = bl & 511;
    __shared__ __align__(16) float stmp[64];
    __shared__ float sq[64];
    __shared__ float so[64];
    __shared__ float rs[8], rq[8];
    int t = threadIdx.x;
    if (t < 64) {
        float ssum = 0.f;
        float v = 0.f;
#pragma unroll
        for (int i = 0; i < 4; i++) {
            ssum += g_sum4[((size_t)(b * 4 + i)) * LL + l];
            v    += g_tmp4[(((size_t)(b * 4 + i)) * LL + l) * NN + t];
        }
        stmp[t] = v / ssum;
        sq[t]   = q[(size_t)bl * DD + t];
    }
    __syncthreads();

    int n4 = t & 15;
    float4 tm = ((float4*)stmp)[n4];
    const float4* vq4 = (const float4*)(vq + (size_t)bl * MM * NN);
    float p[4];
#pragma unroll
    for (int i = 0; i < 4; i++) {
        float4 v = vq4[t + i * 256];
        p[i] = v.x * tm.x + v.y * tm.y + v.z * tm.z + v.w * tm.w;
    }
#pragma unroll
    for (int o = 8; o; o >>= 1)
#pragma unroll
        for (int i = 0; i < 4; i++)
            p[i] += __shfl_down_sync(0xFFFFFFFFu, p[i], o, 16);
    if ((t & 15) == 0) {
        int g = t >> 4;
#pragma unroll
        for (int i = 0; i < 4; i++) so[g + 16 * i] = p[i];
    }
    __syncthreads();

    int m = t & 63;
    float x = sq[m] + so[m];                 // residual (M == D)
    float s1 = x, s2 = x * x;
#pragma unroll
    for (int o = 16; o; o >>= 1) {
        s1 += __shfl_xor_sync(0xFFFFFFFFu, s1, o);
        s2 += __shfl_xor_sync(0xFFFFFFFFu, s2, o);
    }
    int lane = t & 31, w = t >> 5;
    if (lane == 0) { rs[w] = s1; rq[w] = s2; }
    __syncthreads();
    float a = 0.f, b2 = 0.f;
#pragma unroll
    for (int i = 0; i < 8; i++) { a += rs[i]; b2 += rq[i]; }
    float mu   = a * (1.f / 256.f);          // each m replicated 4x -> exact mean
    float var  = b2 * (1.f / 256.f) - mu * mu;
    float rstd = rsqrtf(var + 1e-3f);
    if (t < 64)
        out[(size_t)bl * MM + m] = (x - mu) * rstd * gamma[m] + beta[m];
}

extern "C" void kernel_launch(void* const* d_in, const int* in_sizes, int n_in,
                              void* d_out, int out_size) {
    const float* q     = (const float*)d_in[0];
    const float* k     = (const float*)d_in[1];
    const float* vq    = (const float*)d_in[2];
    const float* vk    = (const float*)d_in[3];
    const float* vexp  = (const float*)d_in[4];
    const float* scale = (const float*)d_in[5];
    const float* gamma = (const float*)d_in[6];
    const float* beta  = (const float*)d_in[7];
    float* out = (float*)d_out;

    int smemS = (128 * KB_STRIDE + 64 * QT_STRIDE + 64) * (int)sizeof(float);
    cudaFuncSetAttribute(sc_kernel, cudaFuncAttributeMaxDynamicSharedMemorySize, smemS);
    int smem2 = (128 * ES + 128 * VS) * (int)sizeof(float);
    cudaFuncSetAttribute(k2_kernel, cudaFuncAttributeMaxDynamicSharedMemorySize, smem2);

    // ---- fork: kv (DRAM-bound) on side stream, sc (fma-bound) on main ----
    cudaStream_t s2;
    cudaStreamCreateWithFlags(&s2, cudaStreamNonBlocking);
    cudaEvent_t eFork, eJoin;
    cudaEventCreateWithFlags(&eFork, cudaEventDisableTiming);
    cudaEventCreateWithFlags(&eJoin, cudaEventDisableTiming);

    cudaEventRecord(eFork, 0);
    cudaStreamWaitEvent(s2, eFork, 0);

    kv_kernel<<<BB * KK / 4, 256, 0, s2>>>(vk, vexp);
    sc_kernel<<<256, 256, smemS>>>(q, k, scale);

    cudaEventRecord(eJoin, s2);
    cudaStreamWaitEvent(0, eJoin, 0);

    // ---- joined: k2 needs both g_ssT (sc) and g_vkc (kv) ----
    k2_kernel<<<256, 256, smem2>>>();
    k3_kernel<<<BB * LL, 256>>>(q, vq, gamma, beta, out);

    cudaEventDestroy(eFork);
    cudaEventDestroy(eJoin);
    cudaStreamDestroy(s2);
}

// round 15
// speedup vs baseline: 1.1783x; 1.1783x over previous
#include <cuda_runtime.h>

#define BB 8
#define LL 512
#define KK 512
#define MM 64
#define NN 64
#define PDIM 64
#define DD 64

// scratch (device globals; no allocations)
__device__ float g_ssT [BB * KK * LL];        // 8 MB  exp(scores) stored [b][k][l]
__device__ float g_sum4[BB * 4 * LL];         // 64 KB per-(b,ktile) partial row sums
__device__ float g_vkc [BB * KK * NN];        // 1 MB
__device__ float g_tmp4[BB * 4 * LL * NN];    // 4 MB  split-K partial tmp

#define KB_STRIDE 68   // kbuf row stride (64 + 4)
#define QT_STRIDE 68   // qT row stride

// ============ Kernel A: block-specialized [scores^T+exp+sums | vkc] ============
// EXACT round-3 version (measured 24.3us with partial overlap).
__global__ void __launch_bounds__(256) ka_kernel(
    const float* __restrict__ q, const float* __restrict__ k,
    const float* __restrict__ vk, const float* __restrict__ vexp,
    const float* __restrict__ scale_p) {
    extern __shared__ float s[];
    int t = threadIdx.x;
    int bid = blockIdx.x;

    if (bid < 256) {
        float* kbuf = s;                        // [128][KB_STRIDE]
        float* qT   = s + 128 * KB_STRIDE;      // [64][QT_STRIDE]
        float* ssum = qT + 64 * QT_STRIDE;      // [64]
        int b  = bid >> 5;
        int r  = bid & 31;
        int l0 = (r >> 2) * 64;
        int kt = r & 3;
        int k0 = kt * 128;

        // load k tile [128][64] coalesced (no transpose needed)
#pragma unroll
        for (int j = 0; j < 8; j++) {
            int v = t + j * 256;
            int row = v >> 4, c4 = v & 15;
            float4 x = *(const float4*)&k[((size_t)(b * KK + k0 + row)) * DD + c4 * 4];
            *(float4*)&kbuf[row * KB_STRIDE + c4 * 4] = x;
        }
        // transpose q tile 64x64 -> qT[d][l]
#pragma unroll
        for (int i = 0; i < 4; i++) {
            int l = (t >> 4) + 16 * i;
            int d4 = t & 15;
            float4 x = *(const float4*)&q[((size_t)(b * LL + l0 + l)) * DD + d4 * 4];
            qT[(d4 * 4 + 0) * QT_STRIDE + l] = x.x;
            qT[(d4 * 4 + 1) * QT_STRIDE + l] = x.y;
            qT[(d4 * 4 + 2) * QT_STRIDE + l] = x.z;
            qT[(d4 * 4 + 3) * QT_STRIDE + l] = x.w;
        }
        if (t < 64) ssum[t] = 0.f;
        __syncthreads();

        // thread tile: 4 k-rows x 8 l-cols
        int tkg = t >> 3;
        int tlg = t & 7;
        float acc[4][8];
#pragma unroll
        for (int a = 0; a < 4; a++)
#pragma unroll
            for (int b2 = 0; b2 < 8; b2++) acc[a][b2] = 0.f;

#pragma unroll 2
        for (int d0 = 0; d0 < DD; d0 += 4) {
            float4 kv[4];
#pragma unroll
            for (int ki = 0; ki < 4; ki++)
                kv[ki] = *(float4*)&kbuf[(tkg * 4 + ki) * KB_STRIDE + d0];
#pragma unroll
            for (int dd = 0; dd < 4; dd++) {
                float4 qa = *(float4*)&qT[(d0 + dd) * QT_STRIDE + tlg * 4];
                float4 qb = *(float4*)&qT[(d0 + dd) * QT_STRIDE + 32 + tlg * 4];
                float kd[4];
                kd[0] = ((float*)&kv[0])[dd];
                kd[1] = ((float*)&kv[1])[dd];
                kd[2] = ((float*)&kv[2])[dd];
                kd[3] = ((float*)&kv[3])[dd];
#pragma unroll
                for (int ki = 0; ki < 4; ki++) {
                    acc[ki][0] += kd[ki] * qa.x;
                    acc[ki][1] += kd[ki] * qa.y;
                    acc[ki][2] += kd[ki] * qa.z;
                    acc[ki][3] += kd[ki] * qa.w;
                    acc[ki][4] += kd[ki] * qb.x;
                    acc[ki][5] += kd[ki] * qb.y;
                    acc[ki][6] += kd[ki] * qb.z;
                    acc[ki][7] += kd[ki] * qb.w;
                }
            }
        }

        // exp, partial row sums, store E^T
        float scale = *scale_p;
        float sacc[8];
#pragma unroll
        for (int j = 0; j < 8; j++) sacc[j] = 0.f;
#pragma unroll
        for (int ki = 0; ki < 4; ki++) {
            float4 e0, e1;
            e0.x = __expf(acc[ki][0] * scale);
            e0.y = __expf(acc[ki][1] * scale);
            e0.z = __expf(acc[ki][2] * scale);
            e0.w = __expf(acc[ki][3] * scale);
            e1.x = __expf(acc[ki][4] * scale);
            e1.y = __expf(acc[ki][5] * scale);
            e1.z = __expf(acc[ki][6] * scale);
            e1.w = __expf(acc[ki][7] * scale);
            sacc[0] += e0.x; sacc[1] += e0.y; sacc[2] += e0.z; sacc[3] += e0.w;
            sacc[4] += e1.x; sacc[5] += e1.y; sacc[6] += e1.z; sacc[7] += e1.w;
            size_t base = ((size_t)(b * KK + k0 + tkg * 4 + ki)) * LL + l0;
            *(float4*)&g_ssT[base + tlg * 4]      = e0;
            *(float4*)&g_ssT[base + 32 + tlg * 4] = e1;
        }
#pragma unroll
        for (int j = 0; j < 4; j++) atomicAdd(&ssum[tlg * 4 + j], sacc[j]);
#pragma unroll
        for (int j = 0; j < 4; j++) atomicAdd(&ssum[32 + tlg * 4 + j], sacc[4 + j]);
        __syncthreads();
        if (t < 64) g_sum4[((size_t)(b * 4 + kt)) * LL + l0 + t] = ssum[t];
    } else {
        // ---- vkc blocks: 2 bk slabs each (exact r3 scalar path) ----
        int idx = bid - 256;                    // 0..2047
#pragma unroll
        for (int rep = 0; rep < 2; rep++) {
            int bk = idx * 2 + rep;
            const float* vkp = vk + (size_t)bk * PDIM * NN;
            const float* ve  = vexp + (size_t)bk * PDIM;
            int n = t & 63, pg = t >> 6;
            float acc = 0.f;
#pragma unroll
            for (int i = 0; i < 16; i++) {
                int p = pg * 16 + i;
                acc += vkp[p * NN + n] * ve[p];
            }
            __syncthreads();
            s[t] = acc;
            __syncthreads();
            if (pg == 0)
                g_vkc[(size_t)bk * NN + n] = s[n] + s[64 + n] + s[128 + n] + s[192 + n];
        }
    }
}

// ============ K2: tmp4 = E^T(chunk) outer-product vkc(chunk), split-K ============
#define ES 68
#define VS 68
__global__ void __launch_bounds__(256) k2_kernel() {
    extern __shared__ float s[];
    float* Es = s;                 // [128][ES]  E^T chunk: [k][l]
    float* Vs = s + 128 * ES;      // [128][VS]  vkc chunk: [k][n]
    int t = threadIdx.x;
    int bid = blockIdx.x;
    int b  = bid >> 5;
    int r  = bid & 31;
    int l0 = (r >> 2) * 64;
    int ks = r & 3;
    int k0 = ks * 128;

#pragma unroll
    for (int j = 0; j < 8; j++) {
        int v = t + j * 256;
        int row = v >> 4, c4 = v & 15;
        float4 x = *(const float4*)&g_ssT[((size_t)(b * KK + k0 + row)) * LL + l0 + c4 * 4];
        *(float4*)&Es[row * ES + c4 * 4] = x;
    }
#pragma unroll
    for (int j = 0; j < 8; j++) {
        int v = t + j * 256;
        int row = v >> 4, c4 = v & 15;
        float4 x = *(const float4*)&g_vkc[((size_t)(b * KK + k0 + row)) * NN + c4 * 4];
        *(float4*)&Vs[row * VS + c4 * 4] = x;
    }
    __syncthreads();

    int tn = t >> 4, tl = t & 15;   // 4l x 4n per thread
    float acc[4][4];
#pragma unroll
    for (int a = 0; a < 4; a++)
#pragma unroll
        for (int b2 = 0; b2 < 4; b2++) acc[a][b2] = 0.f;
#pragma unroll 4
    for (int kk = 0; kk < 128; kk++) {
        float4 e4 = *(float4*)&Es[kk * ES + tl * 4];
        float4 v4 = *(float4*)&Vs[kk * VS + tn * 4];
        float ee[4] = {e4.x, e4.y, e4.z, e4.w};
        float vv[4] = {v4.x, v4.y, v4.z, v4.w};
#pragma unroll
        for (int li = 0; li < 4; li++)
#pragma unroll
            for (int nj = 0; nj < 4; nj++)
                acc[li][nj] += ee[li] * vv[nj];
    }
#pragma unroll
    for (int li = 0; li < 4; li++) {
        int l = l0 + tl * 4 + li;
        float4 o = {acc[li][0], acc[li][1], acc[li][2], acc[li][3]};
        *(float4*)&g_tmp4[(((size_t)(b * 4 + ks)) * LL + l) * NN + tn * 4] = o;
    }
}

// ============ K3: attn = vq @ tmp, residual + LN (2 rows/block, MLP 8) ============
__global__ void __launch_bounds__(256) k3_kernel(
    const float* __restrict__ q, const float* __restrict__ vq,
    const float* __restrict__ gamma, const float* __restrict__ beta,
    float* __restrict__ out) {
    int bl0 = blockIdx.x * 2;        // rows bl0, bl0+1
    int b = bl0 >> 9;
    __shared__ __align__(16) float stmp[2][64];
    __shared__ float sq[2][64];
    __shared__ float so[2][64];
    __shared__ float rs[2][8], rq[2][8];
    int t = threadIdx.x;
    if (t < 128) {
        int rr = t >> 6, tt = t & 63;
        int l = (bl0 & 511) + rr;
        float ssum = 0.f, v = 0.f;
#pragma unroll
        for (int i = 0; i < 4; i++) {
            ssum += g_sum4[((size_t)(b * 4 + i)) * LL + l];
            v    += g_tmp4[(((size_t)(b * 4 + i)) * LL + l) * NN + tt];
        }
        stmp[rr][tt] = v / ssum;
        sq[rr][tt]   = q[(size_t)(bl0 + rr) * DD + tt];
    }
    __syncthreads();

    int n4 = t & 15;
    const float4* vq0 = (const float4*)(vq + (size_t)bl0 * MM * NN);
    const float4* vq1 = vq0 + 1024;
    float4 va[4], vb[4];
#pragma unroll
    for (int i = 0; i < 4; i++) va[i] = vq0[t + i * 256];
#pragma unroll
    for (int i = 0; i < 4; i++) vb[i] = vq1[t + i * 256];

    float4 tm0 = ((float4*)stmp[0])[n4];
    float4 tm1 = ((float4*)stmp[1])[n4];
    float p0[4], p1[4];
#pragma unroll
    for (int i = 0; i < 4; i++) {
        p0[i] = va[i].x * tm0.x + va[i].y * tm0.y + va[i].z * tm0.z + va[i].w * tm0.w;
        p1[i] = vb[i].x * tm1.x + vb[i].y * tm1.y + vb[i].z * tm1.z + vb[i].w * tm1.w;
    }
#pragma unroll
    for (int o = 8; o; o >>= 1)
#pragma unroll
        for (int i = 0; i < 4; i++) {
            p0[i] += __shfl_down_sync(0xFFFFFFFFu, p0[i], o, 16);
            p1[i] += __shfl_down_sync(0xFFFFFFFFu, p1[i], o, 16);
        }
    if ((t & 15) == 0) {
        int g = t >> 4;
#pragma unroll
        for (int i = 0; i < 4; i++) {
            so[0][g + 16 * i] = p0[i];
            so[1][g + 16 * i] = p1[i];
        }
    }
    __syncthreads();

    int m = t & 63;
    int lane = t & 31, w = t >> 5;
    float x0 = sq[0][m] + so[0][m];          // residual (M == D)
    float x1 = sq[1][m] + so[1][m];
    float a0 = x0, q0 = x0 * x0, a1 = x1, q1 = x1 * x1;
#pragma unroll
    for (int o = 16; o; o >>= 1) {
        a0 += __shfl_xor_sync(0xFFFFFFFFu, a0, o);
        q0 += __shfl_xor_sync(0xFFFFFFFFu, q0, o);
        a1 += __shfl_xor_sync(0xFFFFFFFFu, a1, o);
        q1 += __shfl_xor_sync(0xFFFFFFFFu, q1, o);
    }
    if (lane == 0) { rs[0][w] = a0; rq[0][w] = q0; rs[1][w] = a1; rq[1][w] = q1; }
    __syncthreads();
    float sa0 = 0.f, sq0 = 0.f, sa1 = 0.f, sq1 = 0.f;
#pragma unroll
    for (int i = 0; i < 8; i++) {
        sa0 += rs[0][i]; sq0 += rq[0][i];
        sa1 += rs[1][i]; sq1 += rq[1][i];
    }
    if (t < 64) {
        float gm = gamma[m], bt = beta[m];
        float mu0   = sa0 * (1.f / 256.f);   // each m replicated 4x -> exact mean
        float var0  = sq0 * (1.f / 256.f) - mu0 * mu0;
        float mu1   = sa1 * (1.f / 256.f);
        float var1  = sq1 * (1.f / 256.f) - mu1 * mu1;
        out[(size_t)bl0 * MM + m]       = (x0 - mu0) * rsqrtf(var0 + 1e-3f) * gm + bt;
        out[(size_t)(bl0 + 1) * MM + m] = (x1 - mu1) * rsqrtf(var1 + 1e-3f) * gm + bt;
    }
}

extern "C" void kernel_launch(void* const* d_in, const int* in_sizes, int n_in,
                              void* d_out, int out_size) {
    const float* q     = (const float*)d_in[0];
    const float* k     = (const float*)d_in[1];
    const float* vq    = (const float*)d_in[2];
    const float* vk    = (const float*)d_in[3];
    const float* vexp  = (const float*)d_in[4];
    const float* scale = (const float*)d_in[5];
    const float* gamma = (const float*)d_in[6];
    const float* beta  = (const float*)d_in[7];
    float* out = (float*)d_out;

    int smemA = (128 * KB_STRIDE + 64 * QT_STRIDE + 64) * (int)sizeof(float);
    cudaFuncSetAttribute(ka_kernel, cudaFuncAttributeMaxDynamicSharedMemorySize, smemA);
    ka_kernel<<<256 + 2048, 256, smemA>>>(q, k, vk, vexp, scale);

    int smem2 = (128 * ES + 128 * VS) * (int)sizeof(float);
    cudaFuncSetAttribute(k2_kernel, cudaFuncAttributeMaxDynamicSharedMemorySize, smem2);
    k2_kernel<<<256, 256, smem2>>>();

    k3_kernel<<<BB * LL / 2, 256>>>(q, vq, gamma, beta, out);
}

// round 17
// speedup vs baseline: 1.3795x; 1.1708x over previous
#include <cuda_runtime.h>

#define BB 8
#define LL 512
#define KK 512
#define MM 64
#define NN 64
#define PDIM 64
#define DD 64

// scratch (device globals; no allocations)
__device__ float g_ssT [BB * KK * LL];        // 8 MB  exp(scores) stored [b][k][l]
__device__ float g_sum4[BB * 4 * LL];         // 64 KB per-(b,ktile) partial row sums
__device__ float g_vkc [BB * KK * NN];        // 1 MB
__device__ float g_tmp4[BB * 4 * LL * NN];    // 4 MB  split-K partial tmp

#define KB_STRIDE 68
#define QT_STRIDE 68

// ============ SC: scores^T + exp + partial row sums ============
// Triggers PDL completion AT ENTRY so kv co-schedules with its own (tiny) config.
__global__ void __launch_bounds__(256) sc_kernel(
    const float* __restrict__ q, const float* __restrict__ k,
    const float* __restrict__ scale_p) {
#if __CUDA_ARCH__ >= 900
    cudaTriggerProgrammaticLaunchCompletion();
#endif
    extern __shared__ float s[];
    float* kbuf = s;                        // [128][KB_STRIDE]
    float* qT   = s + 128 * KB_STRIDE;      // [64][QT_STRIDE]
    float* ssum = qT + 64 * QT_STRIDE;      // [64]
    int t = threadIdx.x;
    int bid = blockIdx.x;
    int b  = bid >> 5;
    int r  = bid & 31;
    int l0 = (r >> 2) * 64;
    int kt = r & 3;
    int k0 = kt * 128;

#pragma unroll
    for (int j = 0; j < 8; j++) {
        int v = t + j * 256;
        int row = v >> 4, c4 = v & 15;
        float4 x = *(const float4*)&k[((size_t)(b * KK + k0 + row)) * DD + c4 * 4];
        *(float4*)&kbuf[row * KB_STRIDE + c4 * 4] = x;
    }
#pragma unroll
    for (int i = 0; i < 4; i++) {
        int l = (t >> 4) + 16 * i;
        int d4 = t & 15;
        float4 x = *(const float4*)&q[((size_t)(b * LL + l0 + l)) * DD + d4 * 4];
        qT[(d4 * 4 + 0) * QT_STRIDE + l] = x.x;
        qT[(d4 * 4 + 1) * QT_STRIDE + l] = x.y;
        qT[(d4 * 4 + 2) * QT_STRIDE + l] = x.z;
        qT[(d4 * 4 + 3) * QT_STRIDE + l] = x.w;
    }
    if (t < 64) ssum[t] = 0.f;
    __syncthreads();

    int tkg = t >> 3;          // k rows tkg*4..+3
    int tlg = t & 7;           // l groups (tlg*4 and 32+tlg*4)
    float acc[4][8];
#pragma unroll
    for (int a = 0; a < 4; a++)
#pragma unroll
        for (int c = 0; c < 8; c++) acc[a][c] = 0.f;

#pragma unroll 2
    for (int d0 = 0; d0 < DD; d0 += 4) {
        float4 kv4[4];
#pragma unroll
        for (int ki = 0; ki < 4; ki++)
            kv4[ki] = *(float4*)&kbuf[(tkg * 4 + ki) * KB_STRIDE + d0];
#pragma unroll
        for (int dd = 0; dd < 4; dd++) {
            float4 qa = *(float4*)&qT[(d0 + dd) * QT_STRIDE + tlg * 4];
            float4 qb = *(float4*)&qT[(d0 + dd) * QT_STRIDE + 32 + tlg * 4];
            float kd[4];
            kd[0] = ((float*)&kv4[0])[dd];
            kd[1] = ((float*)&kv4[1])[dd];
            kd[2] = ((float*)&kv4[2])[dd];
            kd[3] = ((float*)&kv4[3])[dd];
#pragma unroll
            for (int ki = 0; ki < 4; ki++) {
                acc[ki][0] += kd[ki] * qa.x;
                acc[ki][1] += kd[ki] * qa.y;
                acc[ki][2] += kd[ki] * qa.z;
                acc[ki][3] += kd[ki] * qa.w;
                acc[ki][4] += kd[ki] * qb.x;
                acc[ki][5] += kd[ki] * qb.y;
                acc[ki][6] += kd[ki] * qb.z;
                acc[ki][7] += kd[ki] * qb.w;
            }
        }
    }

    float scale = *scale_p;
    float sacc[8];
#pragma unroll
    for (int j = 0; j < 8; j++) sacc[j] = 0.f;
#pragma unroll
    for (int ki = 0; ki < 4; ki++) {
        float4 e0, e1;
        e0.x = __expf(acc[ki][0] * scale);
        e0.y = __expf(acc[ki][1] * scale);
        e0.z = __expf(acc[ki][2] * scale);
        e0.w = __expf(acc[ki][3] * scale);
        e1.x = __expf(acc[ki][4] * scale);
        e1.y = __expf(acc[ki][5] * scale);
        e1.z = __expf(acc[ki][6] * scale);
        e1.w = __expf(acc[ki][7] * scale);
        sacc[0] += e0.x; sacc[1] += e0.y; sacc[2] += e0.z; sacc[3] += e0.w;
        sacc[4] += e1.x; sacc[5] += e1.y; sacc[6] += e1.z; sacc[7] += e1.w;
        size_t base = ((size_t)(b * KK + k0 + tkg * 4 + ki)) * LL + l0;
        *(float4*)&g_ssT[base + tlg * 4]      = e0;
        *(float4*)&g_ssT[base + 32 + tlg * 4] = e1;
    }
#pragma unroll
    for (int j = 0; j < 4; j++) atomicAdd(&ssum[tlg * 4 + j], sacc[j]);
#pragma unroll
    for (int j = 0; j < 4; j++) atomicAdd(&ssum[32 + tlg * 4 + j], sacc[4 + j]);
    __syncthreads();
    if (t < 64) g_sum4[((size_t)(b * 4 + kt)) * LL + l0 + t] = ssum[t];
}

// ============ KV: vkc stream (PDL-launched; runs CONCURRENT with sc) ============
__global__ void __launch_bounds__(256) kv_kernel(
    const float* __restrict__ vk, const float* __restrict__ vexp) {
    // independent of sc: no cudaGridDependencySynchronize needed
    __shared__ float sve[256];
    __shared__ __align__(16) float4 red[256];
    int t = threadIdx.x;
    int bk0 = blockIdx.x * 4;

    sve[t] = vexp[(size_t)bk0 * PDIM + t];
    __syncthreads();

    int slab = t >> 6;
    int tt = t & 63;
    int n4 = tt & 15;
    int pg = tt >> 4;
    const float4* vk4 = (const float4*)(vk + (size_t)(bk0 + slab) * PDIM * NN);
    const float* ve = &sve[slab * 64];
    float4 acc = make_float4(0.f, 0.f, 0.f, 0.f);
#pragma unroll
    for (int i = 0; i < 16; i++) {
        int p = pg * 16 + i;
        float4 a = vk4[p * 16 + n4];
        float e = ve[p];
        acc.x += a.x * e; acc.y += a.y * e; acc.z += a.z * e; acc.w += a.w * e;
    }
    red[t] = acc;
    __syncthreads();
    if (tt < 16) {
        float4 r0 = red[slab * 64 + n4];
        float4 r1 = red[slab * 64 + 16 + n4];
        float4 r2 = red[slab * 64 + 32 + n4];
        float4 r3 = red[slab * 64 + 48 + n4];
        float4 o = make_float4(r0.x + r1.x + r2.x + r3.x, r0.y + r1.y + r2.y + r3.y,
                               r0.z + r1.z + r2.z + r3.z, r0.w + r1.w + r2.w + r3.w);
        *(float4*)&g_vkc[(size_t)(bk0 + slab) * NN + n4 * 4] = o;
    }
}

// ============ K2: tmp4 = E^T(chunk) outer-product vkc(chunk), split-K ============
#define ES 68
#define VS 68
__global__ void __launch_bounds__(256) k2_kernel() {
#if __CUDA_ARCH__ >= 900
    cudaTriggerProgrammaticLaunchCompletion();   // let k3 prefetch vq while we run
#endif
    extern __shared__ float s[];
    float* Es = s;                 // [128][ES]
    float* Vs = s + 128 * ES;      // [128][VS]
    int t = threadIdx.x;
    int bid = blockIdx.x;
    int b  = bid >> 5;
    int r  = bid & 31;
    int l0 = (r >> 2) * 64;
    int ks = r & 3;
    int k0 = ks * 128;

#pragma unroll
    for (int j = 0; j < 8; j++) {
        int v = t + j * 256;
        int row = v >> 4, c4 = v & 15;
        float4 x = *(const float4*)&g_ssT[((size_t)(b * KK + k0 + row)) * LL + l0 + c4 * 4];
        *(float4*)&Es[row * ES + c4 * 4] = x;
    }
#pragma unroll
    for (int j = 0; j < 8; j++) {
        int v = t + j * 256;
        int row = v >> 4, c4 = v & 15;
        float4 x = *(const float4*)&g_vkc[((size_t)(b * KK + k0 + row)) * NN + c4 * 4];
        *(float4*)&Vs[row * VS + c4 * 4] = x;
    }
    __syncthreads();

    int tn = t >> 4, tl = t & 15;   // 4l x 4n per thread
    float acc[4][4];
#pragma unroll
    for (int a = 0; a < 4; a++)
#pragma unroll
        for (int c = 0; c < 4; c++) acc[a][c] = 0.f;
#pragma unroll 4
    for (int kk = 0; kk < 128; kk++) {
        float4 e4 = *(float4*)&Es[kk * ES + tl * 4];
        float4 v4 = *(float4*)&Vs[kk * VS + tn * 4];
        float ee[4] = {e4.x, e4.y, e4.z, e4.w};
        float vv[4] = {v4.x, v4.y, v4.z, v4.w};
#pragma unroll
        for (int li = 0; li < 4; li++)
#pragma unroll
            for (int nj = 0; nj < 4; nj++)
                acc[li][nj] += ee[li] * vv[nj];
    }
#pragma unroll
    for (int li = 0; li < 4; li++) {
        int l = l0 + tl * 4 + li;
        float4 o = {acc[li][0], acc[li][1], acc[li][2], acc[li][3]};
        *(float4*)&g_tmp4[(((size_t)(b * 4 + ks)) * LL + l) * NN + tn * 4] = o;
    }
}

// ============ K3: attn = vq @ tmp, residual + LN (PDL: vq prefetch pre-sync) ============
__global__ void __launch_bounds__(256) k3_kernel(
    const float* __restrict__ q, const float* __restrict__ vq,
    const float* __restrict__ gamma, const float* __restrict__ beta,
    float* __restrict__ out) {
    int bl = blockIdx.x;             // b*512 + l
    int b = bl >> 9, l = bl & 511;
    __shared__ __align__(16) float stmp[64];
    __shared__ float sq[64];
    __shared__ float so[64];
    __shared__ float rs[8], rq[8];
    int t = threadIdx.x;

    // ---- prefetch independent data (vq row + q) BEFORE the dependency gate ----
    const float4* vq4 = (const float4*)(vq + (size_t)bl * MM * NN);
    float4 va[4];
#pragma unroll
    for (int i = 0; i < 4; i++) va[i] = vq4[t + i * 256];
    float qv = (t < 64) ? q[(size_t)bl * DD + t] : 0.f;

#if __CUDA_ARCH__ >= 900
    cudaGridDependencySynchronize();   // wait for k2's g_tmp4/g_sum4
#endif

    if (t < 64) {
        float ssum = 0.f;
        float v = 0.f;
#pragma unroll
        for (int i = 0; i < 4; i++) {
            ssum += g_sum4[((size_t)(b * 4 + i)) * LL + l];
            v    += g_tmp4[(((size_t)(b * 4 + i)) * LL + l) * NN + t];
        }
        stmp[t] = v / ssum;
        sq[t]   = qv;
    }
    __syncthreads();

    int n4 = t & 15;
    float4 tm = ((float4*)stmp)[n4];
    float p[4];
#pragma unroll
    for (int i = 0; i < 4; i++)
        p[i] = va[i].x * tm.x + va[i].y * tm.y + va[i].z * tm.z + va[i].w * tm.w;
#pragma unroll
    for (int o = 8; o; o >>= 1)
#pragma unroll
        for (int i = 0; i < 4; i++)
            p[i] += __shfl_down_sync(0xFFFFFFFFu, p[i], o, 16);
    if ((t & 15) == 0) {
        int g = t >> 4;
#pragma unroll
        for (int i = 0; i < 4; i++) so[g + 16 * i] = p[i];
    }
    __syncthreads();

    int m = t & 63;
    float x = sq[m] + so[m];                 // residual (M == D)
    float s1 = x, s2 = x * x;
#pragma unroll
    for (int o = 16; o; o >>= 1) {
        s1 += __shfl_xor_sync(0xFFFFFFFFu, s1, o);
        s2 += __shfl_xor_sync(0xFFFFFFFFu, s2, o);
    }
    int lane = t & 31, w = t >> 5;
    if (lane == 0) { rs[w] = s1; rq[w] = s2; }
    __syncthreads();
    float a = 0.f, b2 = 0.f;
#pragma unroll
    for (int i = 0; i < 8; i++) { a += rs[i]; b2 += rq[i]; }
    float mu   = a * (1.f / 256.f);          // each m replicated 4x -> exact mean
    float var  = b2 * (1.f / 256.f) - mu * mu;
    float rstd = rsqrtf(var + 1e-3f);
    if (t < 64)
        out[(size_t)bl * MM + m] = (x - mu) * rstd * gamma[m] + beta[m];
}

extern "C" void kernel_launch(void* const* d_in, const int* in_sizes, int n_in,
                              void* d_out, int out_size) {
    const float* q     = (const float*)d_in[0];
    const float* k     = (const float*)d_in[1];
    const float* vq    = (const float*)d_in[2];
    const float* vk    = (const float*)d_in[3];
    const float* vexp  = (const float*)d_in[4];
    const float* scale = (const float*)d_in[5];
    const float* gamma = (const float*)d_in[6];
    const float* beta  = (const float*)d_in[7];
    float* out = (float*)d_out;

    int smemS = (128 * KB_STRIDE + 64 * QT_STRIDE + 64) * (int)sizeof(float);
    cudaFuncSetAttribute(sc_kernel, cudaFuncAttributeMaxDynamicSharedMemorySize, smemS);
    int smem2 = (128 * ES + 128 * VS) * (int)sizeof(float);
    cudaFuncSetAttribute(k2_kernel, cudaFuncAttributeMaxDynamicSharedMemorySize, smem2);

    // --- sc launches normally, triggers PDL at entry ---
    sc_kernel<<<256, 256, smemS>>>(q, k, scale);

    // --- kv launched with PDL: co-schedules with sc, own (tiny-smem) config ---
    {
        cudaLaunchConfig_t cfg = {};
        cfg.gridDim = dim3(BB * KK / 4);
        cfg.blockDim = dim3(256);
        cfg.dynamicSmemBytes = 0;
        cfg.stream = 0;
        cudaLaunchAttribute attr[1];
        attr[0].id = cudaLaunchAttributeProgrammaticStreamSerialization;
        attr[0].val.programmaticStreamSerializationAllowed = 1;
        cfg.attrs = attr;
        cfg.numAttrs = 1;
        cudaLaunchKernelEx(&cfg, kv_kernel, vk, vexp);
    }

    // --- k2 normal launch: stream-orders after BOTH sc and kv ---
    k2_kernel<<<256, 256, smem2>>>();

    // --- k3 with PDL: prefetches vq while k2 finishes; griddepsync gates tmp4 ---
    {
        cudaLaunchConfig_t cfg = {};
        cfg.gridDim = dim3(BB * LL);
        cfg.blockDim = dim3(256);
        cfg.dynamicSmemBytes = 0;
        cfg.stream = 0;
        cudaLaunchAttribute attr[1];
        attr[0].id = cudaLaunchAttributeProgrammaticStreamSerialization;
        attr[0].val.programmaticStreamSerializationAllowed = 1;
        cfg.attrs = attr;
        cfg.numAttrs = 1;
        cudaLaunchKernelEx(&cfg, k3_kernel, q, vq, gamma, beta, out);
    }
}